// round 9
// baseline (speedup 1.0000x reference)
#include <cuda_runtime.h>
#include <math.h>
#include <stdint.h>

// ---------------- constants ----------------
// B=2, T=2048, NT=4096 tokens, D_MODEL=1024, D_INNER=2048, H_SSM=32, P=64,
// N_STATE=128, CHUNK=256, NCHUNK=8, CONV_DIM=2304, D_IN_PROJ=4384

// ---------------- scratch (device globals; no allocation) ----------------
__device__ float g_qraw[4096u * 1024u];
__device__ float g_resid[4096u * 1024u];
__device__ float g_h[4096u * 1024u];
__device__ float g_zx[4096u * 4384u];        // zxbcdt
__device__ float g_xbc[4096u * 2304u];       // conv+silu output
__device__ float g_acs[2u * 32u * 8u * 256u];          // cumsum(dt*A) [bh][c][l]
__device__ float g_states[2u * 32u * 8u * 64u * 128u]; // per-chunk states [bh][c][p][n]
__device__ float g_prev[2u * 32u * 8u * 64u * 128u];   // scanned prev states
__device__ float g_y[4096u * 2048u];         // ssd output
__device__ float g_y2[4096u * 2048u];        // gated-norm output

__device__ __forceinline__ float softplusf(float v) {
    return (v > 20.f) ? v : log1pf(expf(v));
}

// ---------------- fp32 GEMM: out = A(MxK) @ Bw(NxK)^T (+add) ----
// BM=128, BN=128, BK=16, 256 threads, 8x8 microtile,
// reg-staged prefetch + 2-stage smem double buffer (1 sync per k-iter)
template <int M, int N, int K, bool HASADD, bool NGUARD>
__device__ __forceinline__ void sgemm_body(const float* __restrict__ A,
                                           const float* __restrict__ Bw,
                                           const float* __restrict__ addv,
                                           float* __restrict__ out) {
    __shared__ float As[2][16][132];  // [stage][k][m]
    __shared__ float Bs[2][16][132];  // [stage][k][n]
    const int tid = threadIdx.x;
    const int m0 = blockIdx.y * 128;
    const int n0 = blockIdx.x * 128;
    const int tx = tid & 15;   // n: tx*8
    const int ty = tid >> 4;   // m: ty*8
    float acc[8][8];
#pragma unroll
    for (int i = 0; i < 8; i++)
#pragma unroll
        for (int j = 0; j < 8; j++) acc[i][j] = 0.f;

    const int lr = tid >> 2;          // 0..63
    const int lc = (tid & 3) * 4;     // 0,4,8,12

    float4 ra[2], rb[2];
    // prefetch k0 = 0 and commit to stage 0
#pragma unroll
    for (int i = 0; i < 2; i++) {
        int r = lr + i * 64;
        ra[i] = *reinterpret_cast<const float4*>(A + (size_t)(m0 + r) * K + lc);
        int gn = n0 + r;
        rb[i] = make_float4(0.f, 0.f, 0.f, 0.f);
        if (!NGUARD || gn < N)
            rb[i] = *reinterpret_cast<const float4*>(Bw + (size_t)gn * K + lc);
    }
#pragma unroll
    for (int i = 0; i < 2; i++) {
        int r = lr + i * 64;
        As[0][lc + 0][r] = ra[i].x; As[0][lc + 1][r] = ra[i].y;
        As[0][lc + 2][r] = ra[i].z; As[0][lc + 3][r] = ra[i].w;
        Bs[0][lc + 0][r] = rb[i].x; Bs[0][lc + 1][r] = rb[i].y;
        Bs[0][lc + 2][r] = rb[i].z; Bs[0][lc + 3][r] = rb[i].w;
    }
    __syncthreads();

    int buf = 0;
    for (int k0 = 0; k0 < K; k0 += 16) {
        const bool more = (k0 + 16 < K);
        // issue next tile's global loads first (latency hidden by FMAs below)
        if (more) {
            int kn = k0 + 16;
#pragma unroll
            for (int i = 0; i < 2; i++) {
                int r = lr + i * 64;
                ra[i] = *reinterpret_cast<const float4*>(A + (size_t)(m0 + r) * K + kn + lc);
                int gn = n0 + r;
                rb[i] = make_float4(0.f, 0.f, 0.f, 0.f);
                if (!NGUARD || gn < N)
                    rb[i] = *reinterpret_cast<const float4*>(Bw + (size_t)gn * K + kn + lc);
            }
        }
#pragma unroll
        for (int k = 0; k < 16; k++) {
            float a[8], b[8];
            float4 a0 = *reinterpret_cast<const float4*>(&As[buf][k][ty * 8]);
            float4 a1 = *reinterpret_cast<const float4*>(&As[buf][k][ty * 8 + 4]);
            a[0]=a0.x; a[1]=a0.y; a[2]=a0.z; a[3]=a0.w;
            a[4]=a1.x; a[5]=a1.y; a[6]=a1.z; a[7]=a1.w;
            float4 b0 = *reinterpret_cast<const float4*>(&Bs[buf][k][tx * 8]);
            float4 b1 = *reinterpret_cast<const float4*>(&Bs[buf][k][tx * 8 + 4]);
            b[0]=b0.x; b[1]=b0.y; b[2]=b0.z; b[3]=b0.w;
            b[4]=b1.x; b[5]=b1.y; b[6]=b1.z; b[7]=b1.w;
#pragma unroll
            for (int i = 0; i < 8; i++)
#pragma unroll
                for (int j = 0; j < 8; j++) acc[i][j] = fmaf(a[i], b[j], acc[i][j]);
        }
        if (more) {
            int nb = buf ^ 1;
#pragma unroll
            for (int i = 0; i < 2; i++) {
                int r = lr + i * 64;
                As[nb][lc + 0][r] = ra[i].x; As[nb][lc + 1][r] = ra[i].y;
                As[nb][lc + 2][r] = ra[i].z; As[nb][lc + 3][r] = ra[i].w;
                Bs[nb][lc + 0][r] = rb[i].x; Bs[nb][lc + 1][r] = rb[i].y;
                Bs[nb][lc + 2][r] = rb[i].z; Bs[nb][lc + 3][r] = rb[i].w;
            }
            __syncthreads();   // orders: all reads of buf done + stores to nb visible
            buf = nb;
        }
    }
#pragma unroll
    for (int i = 0; i < 8; i++) {
        int gm = m0 + ty * 8 + i;
#pragma unroll
        for (int j = 0; j < 8; j++) {
            int gn = n0 + tx * 8 + j;
            if (!NGUARD || gn < N) {
                float v = acc[i][j];
                if (HASADD) v += addv[(size_t)gm * N + gn];
                out[(size_t)gm * N + gn] = v;
            }
        }
    }
}

__global__ void __launch_bounds__(256) gemm1_kernel(const float* __restrict__ x,
                                                    const float* __restrict__ W_in) {
    // q = x @ W_in[0:1024]^T   (K/V outputs of the reference are discarded)
    sgemm_body<4096, 1024, 1024, false, false>(x, W_in, nullptr, g_qraw);
}
__global__ void __launch_bounds__(256) gemm2_kernel(const float* __restrict__ Wz) {
    sgemm_body<4096, 4384, 1024, false, true>(g_h, Wz, nullptr, g_zx);
}
__global__ void __launch_bounds__(256) gemm3_kernel(const float* __restrict__ Wout,
                                                    float* __restrict__ out) {
    sgemm_body<4096, 1024, 2048, true, false>(g_y2, Wout, g_resid, out);
}

// ---------------- fused RoPE + pre-RMSNorm ----------------
// one block per token row: resid = rope(qraw); h = rmsnorm(resid)*w
__global__ void rope_norm_kernel(const float* __restrict__ w) {
    int row = blockIdx.x;                       // 0..4095
    int t = row & 2047;
    const float* qr = g_qraw + (size_t)row * 1024;
    __shared__ float sv[1024];
    float ss = 0.f;
#pragma unroll
    for (int u = 0; u < 4; u++) {
        int col = threadIdx.x + u * 256;
        int d = col & 63;
        float v;
        if (d < 32) {
            float inv = expf(-0.28782354222741045f * (float)d);  // ln(1e4)/32
            float f = (float)t * inv;
            v = qr[col] * cosf(f) - qr[col + 32] * sinf(f);
        } else {
            float inv = expf(-0.28782354222741045f * (float)(d - 32));
            float f = (float)t * inv;
            v = qr[col] * cosf(f) + qr[col - 32] * sinf(f);
        }
        sv[col] = v;
        ss += v * v;
    }
    __shared__ float red[8];
#pragma unroll
    for (int o = 16; o > 0; o >>= 1) ss += __shfl_down_sync(0xffffffffu, ss, o);
    if ((threadIdx.x & 31) == 0) red[threadIdx.x >> 5] = ss;
    __syncthreads();
    if (threadIdx.x == 0) {
        float tot = 0.f;
        for (int i = 0; i < 8; i++) tot += red[i];
        red[0] = tot;
    }
    __syncthreads();
    float scale = rsqrtf(red[0] / 1024.f + 1e-5f);
#pragma unroll
    for (int u = 0; u < 4; u++) {
        int col = threadIdx.x + u * 256;
        float v = sv[col];
        g_resid[(size_t)row * 1024 + col] = v;
        g_h[(size_t)row * 1024 + col] = v * scale * w[col];
    }
}

// ---------------- causal conv (width 4) + silu, float4, flattened 1D grid ----
// thread owns one (token, 4-channel group); 4096*576 groups total
__global__ void conv_kernel(const float* __restrict__ conv_w, const float* __restrict__ conv_b) {
    int idx = blockIdx.x * 256 + threadIdx.x;   // < 4096*576
    int bt = idx / 576;
    int c = (idx - bt * 576) * 4;
    int t = bt & 2047;
    // weights: conv_w[c+i][0..3] is contiguous float4
    float4 w0 = *reinterpret_cast<const float4*>(conv_w + (c + 0) * 4);
    float4 w1 = *reinterpret_cast<const float4*>(conv_w + (c + 1) * 4);
    float4 w2 = *reinterpret_cast<const float4*>(conv_w + (c + 2) * 4);
    float4 w3 = *reinterpret_cast<const float4*>(conv_w + (c + 3) * 4);
    float4 bv = *reinterpret_cast<const float4*>(conv_b + c);
    float a0 = bv.x, a1 = bv.y, a2 = bv.z, a3 = bv.w;
#pragma unroll
    for (int k = 0; k < 4; k++) {
        int tt = t - 3 + k;
        if (tt >= 0) {
            float4 xv = *reinterpret_cast<const float4*>(
                g_zx + (size_t)(bt - 3 + k) * 4384 + 2048 + c);
            a0 = fmaf(xv.x, (&w0.x)[k], a0);
            a1 = fmaf(xv.y, (&w1.x)[k], a1);
            a2 = fmaf(xv.z, (&w2.x)[k], a2);
            a3 = fmaf(xv.w, (&w3.x)[k], a3);
        }
    }
    a0 = a0 / (1.f + expf(-a0));
    a1 = a1 / (1.f + expf(-a1));
    a2 = a2 / (1.f + expf(-a2));
    a3 = a3 / (1.f + expf(-a3));
    *reinterpret_cast<float4*>(g_xbc + (size_t)bt * 2304 + c) = make_float4(a0, a1, a2, a3);
}

// ---------------- SSD stage A: cumsum + per-chunk states ----------------
// dt computed inline: dt = softplus(zx[...,4352+h] + dt_bias[h])
__global__ void ssd_states_kernel(const float* __restrict__ A_log,
                                  const float* __restrict__ dt_bias) {
    int c = blockIdx.x;        // 0..7
    int bh = blockIdx.y;       // 0..63
    int b = bh >> 5, h = bh & 31;
    int bt0 = b * 2048 + c * 256;
    int tid = threadIdx.x;
    int lane = tid & 31, wid = tid >> 5;

    __shared__ float sAcs[256];
    __shared__ float sdt[256];
    __shared__ float wsum[8];

    float Aneg = -expf(A_log[h]);
    float dtv = softplusf(g_zx[(size_t)(bt0 + tid) * 4384 + 4352 + h] + dt_bias[h]);
    sdt[tid] = dtv;
    // inclusive scan of dtv*Aneg: warp shfl scan + warp-sum prefix
    float v = dtv * Aneg;
#pragma unroll
    for (int off = 1; off < 32; off <<= 1) {
        float nv = __shfl_up_sync(0xffffffffu, v, off);
        if (lane >= off) v += nv;
    }
    if (lane == 31) wsum[wid] = v;
    __syncthreads();
    float base = 0.f;
#pragma unroll
    for (int wv = 0; wv < 8; wv++)
        if (wv < wid) base += wsum[wv];
    v += base;
    sAcs[tid] = v;
    g_acs[((size_t)bh * 8 + c) * 256 + tid] = v;
    __syncthreads();
    float Alast = sAcs[255];

    const int tx = tid & 15;  // n: tx*8
    const int ty = tid >> 4;  // p: ty*4
    float acc[4][8];
#pragma unroll
    for (int i = 0; i < 4; i++)
#pragma unroll
        for (int j = 0; j < 8; j++) acc[i][j] = 0.f;

    __shared__ float Xs[16][68];   // [l][p] (scale folded)
    __shared__ float Bsh[16][132]; // [l][n]

    for (int l0 = 0; l0 < 256; l0 += 16) {
        {
            int l = tid >> 4, p4 = (tid & 15) * 4;
            int bt = bt0 + l0 + l;
            float sc = sdt[l0 + l] * expf(Alast - sAcs[l0 + l]);
            float4 vv = *reinterpret_cast<const float4*>(g_xbc + (size_t)bt * 2304 + h * 64 + p4);
            Xs[l][p4 + 0] = vv.x * sc; Xs[l][p4 + 1] = vv.y * sc;
            Xs[l][p4 + 2] = vv.z * sc; Xs[l][p4 + 3] = vv.w * sc;
        }
#pragma unroll
        for (int i = 0; i < 2; i++) {
            int idx = tid + i * 256;
            int l = idx >> 5, n4 = (idx & 31) * 4;
            int bt = bt0 + l0 + l;
            float4 vv = *reinterpret_cast<const float4*>(g_xbc + (size_t)bt * 2304 + 2048 + n4);
            Bsh[l][n4 + 0] = vv.x; Bsh[l][n4 + 1] = vv.y;
            Bsh[l][n4 + 2] = vv.z; Bsh[l][n4 + 3] = vv.w;
        }
        __syncthreads();
#pragma unroll
        for (int k = 0; k < 16; k++) {
            float xv[4], bv[8];
#pragma unroll
            for (int i = 0; i < 4; i++) xv[i] = Xs[k][ty * 4 + i];
#pragma unroll
            for (int j = 0; j < 8; j++) bv[j] = Bsh[k][tx * 8 + j];
#pragma unroll
            for (int i = 0; i < 4; i++)
#pragma unroll
                for (int j = 0; j < 8; j++) acc[i][j] = fmaf(xv[i], bv[j], acc[i][j]);
        }
        __syncthreads();
    }
    float* st = g_states + ((size_t)bh * 8 + c) * 8192;
#pragma unroll
    for (int i = 0; i < 4; i++)
#pragma unroll
        for (int j = 0; j < 8; j++)
            st[(ty * 4 + i) * 128 + (tx * 8 + j)] = acc[i][j];
}

// ---------------- SSD stage B: inter-chunk scan (float4) ----------------
__global__ void ssd_scan_kernel() {
    int bh = blockIdx.x;
    __shared__ float sAt[8];
    if (threadIdx.x < 8)
        sAt[threadIdx.x] = expf(g_acs[((size_t)bh * 8 + threadIdx.x) * 256 + 255]);
    __syncthreads();
    for (int e4 = threadIdx.x; e4 < 2048; e4 += 256) {
        float4 P = make_float4(0.f, 0.f, 0.f, 0.f);
#pragma unroll
        for (int c = 0; c < 8; c++) {
            size_t off = ((size_t)bh * 8 + c) * 8192 + e4 * 4;
            *reinterpret_cast<float4*>(g_prev + off) = P;
            float4 S = *reinterpret_cast<const float4*>(g_states + off);
            float a = sAt[c];
            P.x = fmaf(P.x, a, S.x); P.y = fmaf(P.y, a, S.y);
            P.z = fmaf(P.z, a, S.z); P.w = fmaf(P.w, a, S.w);
        }
    }
}

// ---------------- SSD fused Y: Y = sum_s G(l,s)X(s,:) + exp(Acs_l)*C@P^T + D*x ----
// G(l,s) = [s<=l] * exp(Acs_l - Acs_s) * dt_s * (C_l . B_s)   (never materialized)
// block = (tl 0..3, c 0..7, bh 0..63), 256 threads, 64x64 output tile, 4x4 micro
__global__ void ssd_fused_y_kernel(const float* __restrict__ D_param,
                                   const float* __restrict__ dt_bias) {
    int tl = blockIdx.x;   // 64-row l tile
    int c = blockIdx.y;
    int bh = blockIdx.z;
    int b = bh >> 5, h = bh & 31;
    int bt0 = b * 2048 + c * 256;
    int l0 = tl * 64;
    int tid = threadIdx.x;
    const int tx = tid & 15, ty = tid >> 4;

    __shared__ float As[16][68];   // step-1 C tile [n][l] / step-off C tile
    __shared__ float Bs[16][68];   // step-1 B tile [n][s] / step-2 X tile [k][p]
    __shared__ float St[64][65];   // scaled G tile, TRANSPOSED: St[s][l]
    __shared__ float sAcs[256];
    __shared__ float sDt[256];

    sAcs[tid] = g_acs[((size_t)bh * 8 + c) * 256 + tid];
    sDt[tid]  = softplusf(g_zx[(size_t)(bt0 + tid) * 4384 + 4352 + h] + dt_bias[h]);
    __syncthreads();

    float Yacc[4][4];
#pragma unroll
    for (int i = 0; i < 4; i++)
#pragma unroll
        for (int j = 0; j < 4; j++) Yacc[i][j] = 0.f;

    const int lr = tid >> 2;          // 0..63
    const int lc = (tid & 3) * 4;     // 0,4,8,12

    for (int st = 0; st <= tl; st++) {
        int s0 = st * 64;
        // ---- step 1: Sacc = C[l0..] @ B[s0..]^T over n=128 ----
        float Sacc[4][4];
#pragma unroll
        for (int i = 0; i < 4; i++)
#pragma unroll
            for (int j = 0; j < 4; j++) Sacc[i][j] = 0.f;
        for (int n0 = 0; n0 < 128; n0 += 16) {
            float4 v = *reinterpret_cast<const float4*>(
                g_xbc + (size_t)(bt0 + l0 + lr) * 2304 + 2176 + n0 + lc);
            As[lc + 0][lr] = v.x; As[lc + 1][lr] = v.y;
            As[lc + 2][lr] = v.z; As[lc + 3][lr] = v.w;
            float4 w = *reinterpret_cast<const float4*>(
                g_xbc + (size_t)(bt0 + s0 + lr) * 2304 + 2048 + n0 + lc);
            Bs[lc + 0][lr] = w.x; Bs[lc + 1][lr] = w.y;
            Bs[lc + 2][lr] = w.z; Bs[lc + 3][lr] = w.w;
            __syncthreads();
#pragma unroll
            for (int k = 0; k < 16; k++) {
                float a[4], bb[4];
#pragma unroll
                for (int i = 0; i < 4; i++) a[i] = As[k][ty * 4 + i];
#pragma unroll
                for (int j = 0; j < 4; j++) bb[j] = Bs[k][tx * 4 + j];
#pragma unroll
                for (int i = 0; i < 4; i++)
#pragma unroll
                    for (int j = 0; j < 4; j++) Sacc[i][j] = fmaf(a[i], bb[j], Sacc[i][j]);
            }
            __syncthreads();
        }
        // ---- scale + mask, store transposed into St[s][l] ----
#pragma unroll
        for (int i = 0; i < 4; i++) {
            int lg = l0 + ty * 4 + i;         // 0..255 in-chunk l
            float la = sAcs[lg];
#pragma unroll
            for (int j = 0; j < 4; j++) {
                int sg = s0 + tx * 4 + j;     // 0..255 in-chunk s
                float val = 0.f;
                if (sg <= lg)
                    val = expf(la - sAcs[sg]) * sDt[sg] * Sacc[i][j];
                St[sg - s0][ty * 4 + i] = val;
            }
        }
        __syncthreads();
        // ---- step 2: Yacc += St^T @ X[s0..]  (k = s index within tile) ----
        for (int k0 = 0; k0 < 64; k0 += 16) {
            int kk = tid >> 4, p4 = (tid & 15) * 4;
            float4 xv = *reinterpret_cast<const float4*>(
                g_xbc + (size_t)(bt0 + s0 + k0 + kk) * 2304 + h * 64 + p4);
            Bs[kk][p4 + 0] = xv.x; Bs[kk][p4 + 1] = xv.y;
            Bs[kk][p4 + 2] = xv.z; Bs[kk][p4 + 3] = xv.w;
            __syncthreads();
#pragma unroll
            for (int k = 0; k < 16; k++) {
                float a[4], bb[4];
#pragma unroll
                for (int i = 0; i < 4; i++) a[i] = St[k0 + k][ty * 4 + i];
#pragma unroll
                for (int j = 0; j < 4; j++) bb[j] = Bs[k][tx * 4 + j];
#pragma unroll
                for (int i = 0; i < 4; i++)
#pragma unroll
                    for (int j = 0; j < 4; j++) Yacc[i][j] = fmaf(a[i], bb[j], Yacc[i][j]);
            }
            __syncthreads();
        }
    }

    // ---- off-diagonal: Yacc += (exp(Acs_l)*C) @ P^T ----
    const float* P = g_prev + ((size_t)bh * 8 + c) * 8192;
    for (int n0 = 0; n0 < 128; n0 += 16) {
        {
            float4 cv = *reinterpret_cast<const float4*>(
                g_xbc + (size_t)(bt0 + l0 + lr) * 2304 + 2176 + n0 + lc);
            float e = expf(sAcs[l0 + lr]);
            As[lc + 0][lr] = cv.x * e; As[lc + 1][lr] = cv.y * e;
            As[lc + 2][lr] = cv.z * e; As[lc + 3][lr] = cv.w * e;
        }
        {
            float4 pv = *reinterpret_cast<const float4*>(P + (size_t)lr * 128 + n0 + lc);
            Bs[lc + 0][lr] = pv.x; Bs[lc + 1][lr] = pv.y;
            Bs[lc + 2][lr] = pv.z; Bs[lc + 3][lr] = pv.w;
        }
        __syncthreads();
#pragma unroll
        for (int k = 0; k < 16; k++) {
            float a[4], bb[4];
#pragma unroll
            for (int i = 0; i < 4; i++) a[i] = As[k][ty * 4 + i];
#pragma unroll
            for (int j = 0; j < 4; j++) bb[j] = Bs[k][tx * 4 + j];
#pragma unroll
            for (int i = 0; i < 4; i++)
#pragma unroll
                for (int j = 0; j < 4; j++) Yacc[i][j] = fmaf(a[i], bb[j], Yacc[i][j]);
        }
        __syncthreads();
    }

    // ---- epilogue: + D*x, write y token-major ----
    float Dv = D_param[h];
#pragma unroll
    for (int i = 0; i < 4; i++) {
        int bt = bt0 + l0 + ty * 4 + i;
#pragma unroll
        for (int j = 0; j < 4; j++) {
            int p = tx * 4 + j;
            float xv = g_xbc[(size_t)bt * 2304 + h * 64 + p];
            g_y[(size_t)bt * 2048 + h * 64 + p] = Yacc[i][j] + Dv * xv;
        }
    }
}

// ---------------- gated RMSNorm: y2 = rmsnorm(y * silu(z)) * w ----------------
// register-resident: thread owns 8 contiguous channels (2 float4s)
__global__ void gated_norm_kernel(const float* __restrict__ w) {
    int row = blockIdx.x;
    const float* yr = g_y + (size_t)row * 2048;
    const float* zr = g_zx + (size_t)row * 4384;  // z = first 2048 of zxbcdt
    int base = threadIdx.x * 8;
    float v[8];
    float ss = 0.f;
#pragma unroll
    for (int q = 0; q < 2; q++) {
        float4 yv = *reinterpret_cast<const float4*>(yr + base + q * 4);
        float4 zv = *reinterpret_cast<const float4*>(zr + base + q * 4);
        float* vp = v + q * 4;
        vp[0] = yv.x * (zv.x / (1.f + expf(-zv.x)));
        vp[1] = yv.y * (zv.y / (1.f + expf(-zv.y)));
        vp[2] = yv.z * (zv.z / (1.f + expf(-zv.z)));
        vp[3] = yv.w * (zv.w / (1.f + expf(-zv.w)));
        ss += vp[0]*vp[0] + vp[1]*vp[1] + vp[2]*vp[2] + vp[3]*vp[3];
    }
    __shared__ float red[8];
#pragma unroll
    for (int o = 16; o > 0; o >>= 1) ss += __shfl_down_sync(0xffffffffu, ss, o);
    if ((threadIdx.x & 31) == 0) red[threadIdx.x >> 5] = ss;
    __syncthreads();
    if (threadIdx.x == 0) {
        float t = 0.f;
        for (int i = 0; i < 8; i++) t += red[i];
        red[0] = t;
    }
    __syncthreads();
    float scale = rsqrtf(red[0] / 2048.f + 1e-5f);
    float* outp = g_y2 + (size_t)row * 2048 + base;
#pragma unroll
    for (int q = 0; q < 2; q++) {
        float4 wv = *reinterpret_cast<const float4*>(w + base + q * 4);
        float* vp = v + q * 4;
        *reinterpret_cast<float4*>(outp + q * 4) = make_float4(
            vp[0] * scale * wv.x, vp[1] * scale * wv.y,
            vp[2] * scale * wv.z, vp[3] * scale * wv.w);
    }
}

// ---------------- launch ----------------
extern "C" void kernel_launch(void* const* d_in, const int* in_sizes, int n_in,
                              void* d_out, int out_size) {
    const float* x            = (const float*)d_in[0];
    const float* W_in         = (const float*)d_in[1];
    const float* W_zxbcdt     = (const float*)d_in[2];
    const float* conv_w       = (const float*)d_in[3];
    const float* conv_b       = (const float*)d_in[4];
    const float* dt_bias      = (const float*)d_in[5];
    const float* A_log        = (const float*)d_in[6];
    const float* D_param      = (const float*)d_in[7];
    const float* norm_pre_w   = (const float*)d_in[8];
    const float* norm_gated_w = (const float*)d_in[9];
    const float* W_out        = (const float*)d_in[10];
    float* out = (float*)d_out;

    gemm1_kernel<<<dim3(8, 32), 256>>>(x, W_in);               // q = x @ W_in[:1024]^T
    rope_norm_kernel<<<4096, 256>>>(norm_pre_w);               // resid=rope(q); h=rmsnorm
    gemm2_kernel<<<dim3(35, 32), 256>>>(W_zxbcdt);             // zxbcdt = h @ Wz^T
    conv_kernel<<<9216, 256>>>(conv_w, conv_b);                // xBC = silu(conv(xBC))
    ssd_states_kernel<<<dim3(8, 64), 256>>>(A_log, dt_bias);   // Acs + chunk states
    ssd_scan_kernel<<<64, 256>>>();                            // inter-chunk scan
    ssd_fused_y_kernel<<<dim3(4, 8, 64), 256>>>(D_param, dt_bias); // fused G + Y
    gated_norm_kernel<<<4096, 256>>>(norm_gated_w);            // y2 = rmsnorm(y*silu(z))
    gemm3_kernel<<<dim3(8, 32), 256>>>(W_out, out);            // out = y2 @ Wout^T + resid
}